// round 5
// baseline (speedup 1.0000x reference)
#include <cuda_runtime.h>
#include <cuda_fp16.h>
#include <math.h>
#include <stdint.h>

#define BB 4
#define SS 512
#define DD 4096
#define HH 32
#define HKV 8
#define HD 128
#define STARTP 512
#define TT 1024
#define MTOK (BB*SS)

// ---------------- scratch (static device globals) ----------------------------
__device__ float g_scores[(size_t)BB * HH * SS * TT];   // 268 MB

__device__ __half g_xhi[(size_t)MTOK * DD],  g_xlo[(size_t)MTOK * DD];
__device__ __half g_wqhi[(size_t)DD * DD],   g_wqlo[(size_t)DD * DD];
__device__ __half g_wkhi[(size_t)HKV*HD*DD], g_wklo[(size_t)HKV*HD*DD];
__device__ __half g_wvhi[(size_t)HKV*HD*DD], g_wvlo[(size_t)HKV*HD*DD];
__device__ __half g_wohi[(size_t)DD * DD],   g_wolo[(size_t)DD * DD];
__device__ __half g_qhi[(size_t)MTOK * DD],  g_qlo[(size_t)MTOK * DD];
__device__ __half g_kthi[(size_t)MTOK*HKV*HD], g_ktlo[(size_t)MTOK*HKV*HD];
__device__ __half g_vthi[(size_t)MTOK*HKV*HD], g_vtlo[(size_t)MTOK*HKV*HD];
__device__ __half g_khi[(size_t)BB*TT*HKV*HD], g_klo[(size_t)BB*TT*HKV*HD];
__device__ __half g_vThi[(size_t)BB*HKV*HD*TT], g_vTlo[(size_t)BB*HKV*HD*TT];
__device__ __half g_phi[(size_t)BB*HH*SS*TT], g_plo[(size_t)BB*HH*SS*TT];
__device__ __half g_ahi[(size_t)MTOK * DD],  g_alo[(size_t)MTOK * DD];

// ---------------- PTX helpers ------------------------------------------------
__device__ __forceinline__ uint32_t smem_u32(const void* p){
    uint32_t a;
    asm("{ .reg .u64 t; cvta.to.shared.u64 t, %1; cvt.u32.u64 %0, t; }" : "=r"(a) : "l"(p));
    return a;
}
__device__ __forceinline__ void cpasync16(uint32_t d, const void* g){
    asm volatile("cp.async.cg.shared.global [%0], [%1], 16;" :: "r"(d), "l"(g));
}
__device__ __forceinline__ void ldsm4(uint32_t* x, uint32_t a){
    asm volatile("ldmatrix.sync.aligned.m8n8.x4.shared.b16 {%0,%1,%2,%3}, [%4];"
        : "=r"(x[0]), "=r"(x[1]), "=r"(x[2]), "=r"(x[3]) : "r"(a));
}
__device__ __forceinline__ void mma16816(float* d, const uint32_t* a, uint32_t b0, uint32_t b1){
    asm volatile("mma.sync.aligned.m16n8k16.row.col.f32.f16.f16.f32 "
        "{%0,%1,%2,%3}, {%4,%5,%6,%7}, {%8,%9}, {%0,%1,%2,%3};"
        : "+f"(d[0]), "+f"(d[1]), "+f"(d[2]), "+f"(d[3])
        : "r"(a[0]), "r"(a[1]), "r"(a[2]), "r"(a[3]), "r"(b0), "r"(b1));
}

// smem (halves): per buffer  Ah@0  Al@5120  Bh@10240  Bl@15360 ; pitch 40 halves
#define PITCH 40
#define ABYTES 10240
#define BUFBYTES 40960
#define DSMEM 81920

// ---------------- split-f16 HMMA GEMM core -----------------------------------
// C[M,N] = alpha * A * B^T ;  A[M,K] hi/lo (lda), B[N,K] hi/lo (ldb)
// A*B ~= Ah*Bh + Ah*Bl + Al*Bh.  EPI=0: fp32 C.  EPI=1: split-f16 Chi/Clo.
template<int EPI>
__device__ __forceinline__ void mma_core(
    const __half* __restrict__ Ahi, const __half* __restrict__ Alo, int lda,
    const __half* __restrict__ Bhi, const __half* __restrict__ Blo, int ldb,
    float* __restrict__ C, __half* __restrict__ Chi, __half* __restrict__ Clo, int ldc,
    int K, float alpha, int bm, int bn)
{
    extern __shared__ __half sm[];
    const uint32_t sbase = smem_u32(sm);
    const int tid  = threadIdx.x;
    const int lane = tid & 31, wid = tid >> 5;
    const int wm = (wid & 3) * 32;
    const int wn = (wid >> 2) * 64;

    float acc[2][8][4];
#pragma unroll
    for (int i = 0; i < 2; i++)
#pragma unroll
        for (int j = 0; j < 8; j++)
#pragma unroll
            for (int k = 0; k < 4; k++) acc[i][j][k] = 0.0f;

    const int q = lane >> 3, r = lane & 7;
    const uint32_t offA = (uint32_t)(((wm + (q & 1) * 8 + r) * PITCH + (q >> 1) * 8) * 2);
    const uint32_t offB = (uint32_t)(((wn + (q >> 1) * 8 + r) * PITCH + (q & 1) * 8) * 2);

    const int row0 = tid >> 2, seg0 = (tid & 3) * 8;
    const int row1 = (tid + 256) >> 2, seg1 = ((tid + 256) & 3) * 8;

    const int NC = K >> 5;

#define LOAD_CHUNK(c, buf) do {                                                  \
    uint32_t db = sbase + (buf) * BUFBYTES;                                      \
    const __half* a0 = Ahi + (size_t)(bm + row0) * lda + (c) * 32 + seg0;        \
    const __half* l0 = Alo + (size_t)(bm + row0) * lda + (c) * 32 + seg0;        \
    const __half* b0 = Bhi + (size_t)(bn + row0) * ldb + (c) * 32 + seg0;        \
    const __half* c0 = Blo + (size_t)(bn + row0) * ldb + (c) * 32 + seg0;        \
    uint32_t d0 = db + (uint32_t)(row0 * PITCH + seg0) * 2;                      \
    cpasync16(d0, a0);  cpasync16(d0 + ABYTES, l0);                              \
    cpasync16(d0 + 2*ABYTES, b0);  cpasync16(d0 + 3*ABYTES, c0);                 \
    const __half* a1 = Ahi + (size_t)(bm + row1) * lda + (c) * 32 + seg1;        \
    const __half* l1 = Alo + (size_t)(bm + row1) * lda + (c) * 32 + seg1;        \
    const __half* b1 = Bhi + (size_t)(bn + row1) * ldb + (c) * 32 + seg1;        \
    const __half* c1 = Blo + (size_t)(bn + row1) * ldb + (c) * 32 + seg1;        \
    uint32_t d1 = db + (uint32_t)(row1 * PITCH + seg1) * 2;                      \
    cpasync16(d1, a1);  cpasync16(d1 + ABYTES, l1);                              \
    cpasync16(d1 + 2*ABYTES, b1);  cpasync16(d1 + 3*ABYTES, c1);                 \
    asm volatile("cp.async.commit_group;" ::: "memory");                         \
} while (0)

    LOAD_CHUNK(0, 0);

    for (int c = 0; c < NC; ++c) {
        if (c + 1 < NC) {
            LOAD_CHUNK(c + 1, (c + 1) & 1);
            asm volatile("cp.async.wait_group 1;" ::: "memory");
        } else {
            asm volatile("cp.async.wait_group 0;" ::: "memory");
        }
        __syncthreads();

        uint32_t base = sbase + (c & 1) * BUFBYTES;
#pragma unroll
        for (int ks = 0; ks < 2; ks++) {
            const uint32_t kso = (uint32_t)(ks * 16 * 2);
            uint32_t ah[2][4], al[2][4];
#pragma unroll
            for (int mt = 0; mt < 2; mt++) {
                uint32_t o = base + offA + (uint32_t)(mt * 16 * PITCH * 2) + kso;
                ldsm4(ah[mt], o);
                ldsm4(al[mt], o + ABYTES);
            }
#pragma unroll
            for (int j = 0; j < 4; j++) {
                uint32_t bh[4], bl[4];
                uint32_t o = base + 2 * ABYTES + offB + (uint32_t)(j * 16 * PITCH * 2) + kso;
                ldsm4(bh, o);
                ldsm4(bl, o + ABYTES);
#pragma unroll
                for (int mt = 0; mt < 2; mt++) {
                    mma16816(acc[mt][2*j],   ah[mt], bh[0], bh[1]);
                    mma16816(acc[mt][2*j],   ah[mt], bl[0], bl[1]);
                    mma16816(acc[mt][2*j],   al[mt], bh[0], bh[1]);
                    mma16816(acc[mt][2*j+1], ah[mt], bh[2], bh[3]);
                    mma16816(acc[mt][2*j+1], ah[mt], bl[2], bl[3]);
                    mma16816(acc[mt][2*j+1], al[mt], bh[2], bh[3]);
                }
            }
        }
        __syncthreads();
    }
#undef LOAD_CHUNK

    const int er = bm + wm + (lane >> 2);
    const int ec = bn + wn + 2 * (lane & 3);
#pragma unroll
    for (int mt = 0; mt < 2; mt++)
#pragma unroll
        for (int nt = 0; nt < 8; nt++) {
            int rr = er + mt * 16;
            int cc = ec + nt * 8;
            float v0 = alpha * acc[mt][nt][0];
            float v1 = alpha * acc[mt][nt][1];
            float v2 = alpha * acc[mt][nt][2];
            float v3 = alpha * acc[mt][nt][3];
            if (EPI == 0) {
                *(float2*)(C + (size_t)rr * ldc + cc)       = make_float2(v0, v1);
                *(float2*)(C + (size_t)(rr + 8) * ldc + cc) = make_float2(v2, v3);
            } else {
                __half h0 = __float2half_rn(v0), h1 = __float2half_rn(v1);
                __half h2 = __float2half_rn(v2), h3 = __float2half_rn(v3);
                *(__half2*)(Chi + (size_t)rr * ldc + cc) = __halves2half2(h0, h1);
                *(__half2*)(Clo + (size_t)rr * ldc + cc) = __halves2half2(
                    __float2half_rn(v0 - __half2float(h0)), __float2half_rn(v1 - __half2float(h1)));
                *(__half2*)(Chi + (size_t)(rr + 8) * ldc + cc) = __halves2half2(h2, h3);
                *(__half2*)(Clo + (size_t)(rr + 8) * ldc + cc) = __halves2half2(
                    __float2half_rn(v2 - __half2float(h2)), __float2half_rn(v3 - __half2float(h3)));
            }
        }
}

// fused QKV projection: blockIdx.x selects weight/output
__global__ __launch_bounds__(256, 2) void tc_qkv()
{
    int j = blockIdx.x;
    int bm = blockIdx.y * 128;
    if (j < 32) {
        mma_core<1>(g_xhi, g_xlo, DD, g_wqhi, g_wqlo, DD,
                    nullptr, g_qhi, g_qlo, DD, DD, 1.0f, bm, j * 128);
    } else if (j < 40) {
        mma_core<1>(g_xhi, g_xlo, DD, g_wkhi, g_wklo, DD,
                    nullptr, g_kthi, g_ktlo, HKV * HD, DD, 1.0f, bm, (j - 32) * 128);
    } else {
        mma_core<1>(g_xhi, g_xlo, DD, g_wvhi, g_wvlo, DD,
                    nullptr, g_vthi, g_vtlo, HKV * HD, DD, 1.0f, bm, (j - 40) * 128);
    }
}

__global__ __launch_bounds__(256, 2) void tc_wo(float* __restrict__ out)
{
    mma_core<0>(g_ahi, g_alo, DD, g_wohi, g_wolo, DD,
                out, nullptr, nullptr, DD, DD, 1.0f, blockIdx.y * 128, blockIdx.x * 128);
}

__global__ __launch_bounds__(256, 2) void tc_scores()
{
    int z = blockIdx.z; int b = z >> 5, h = z & 31, kv = h >> 2;
    size_t ao = (size_t)b * SS * DD + (size_t)h * HD;
    size_t bo = ((size_t)b * TT * HKV + kv) * HD;
    mma_core<0>(g_qhi + ao, g_qlo + ao, DD, g_khi + bo, g_klo + bo, HKV * HD,
                g_scores + (size_t)z * SS * TT, nullptr, nullptr, TT, HD,
                0.08838834764831843f, blockIdx.y * 128, blockIdx.x * 128);
}

__global__ __launch_bounds__(256, 2) void tc_pv()
{
    int z = blockIdx.z; int b = z >> 5, h = z & 31, kv = h >> 2;
    size_t ao = (size_t)z * SS * TT;
    size_t bo = ((size_t)(b * HKV + kv) * HD) * TT;
    size_t co = ((size_t)b * SS * HH + h) * HD;
    mma_core<1>(g_phi + ao, g_plo + ao, TT, g_vThi + bo, g_vTlo + bo, TT,
                nullptr, g_ahi + co, g_alo + co, DD, TT, 1.0f, blockIdx.y * 128, 0);
}

// ---------------- elementwise / setup ----------------------------------------
#define NX  (MTOK * DD)                 // 8388608
#define NWQ (DD * DD)                   // 16777216
#define NWK (HKV * HD * DD)             // 4194304
#define NTOT (NX + NWQ + 2 * NWK + NWQ) // 50331648

__global__ void split_all(const float* __restrict__ x,  const float* __restrict__ wq,
                          const float* __restrict__ wk, const float* __restrict__ wv,
                          const float* __restrict__ wo)
{
    for (int i = blockIdx.x * blockDim.x + threadIdx.x; i < NTOT; i += gridDim.x * blockDim.x) {
        const float* src; __half *hi, *lo; int o = i;
        if (o < NX)                 { src = x;  hi = g_xhi;  lo = g_xlo; }
        else if ((o -= NX)  < NWQ)  { src = wq; hi = g_wqhi; lo = g_wqlo; }
        else if ((o -= NWQ) < NWK)  { src = wk; hi = g_wkhi; lo = g_wklo; }
        else if ((o -= NWK) < NWK)  { src = wv; hi = g_wvhi; lo = g_wvlo; }
        else  { o -= NWK;             src = wo; hi = g_wohi; lo = g_wolo; }
        float v = src[o];
        __half h = __float2half_rn(v);
        hi[o] = h;
        lo[o] = __float2half_rn(v - __half2float(h));
    }
}

__global__ void rope_q_kernel(const float* __restrict__ fc, const float* __restrict__ fs)
{
    int idx = blockIdx.x * blockDim.x + threadIdx.x;    // BB*SS*HH*64 pairs
    int p = idx & 63; int rest = idx >> 6;
    int h = rest & 31; rest >>= 5;
    int s = rest & 511; int b = rest >> 9;
    float c  = fc[s * 64 + p];
    float si = fs[s * 64 + p];
    size_t o = ((size_t)(b * SS + s) * HH + h) * HD + 2 * p;
    float a  = __half2float(g_qhi[o])     + __half2float(g_qlo[o]);
    float bb = __half2float(g_qhi[o + 1]) + __half2float(g_qlo[o + 1]);
    float o0 = a * c - bb * si, o1 = a * si + bb * c;
    __half h0 = __float2half_rn(o0), h1 = __float2half_rn(o1);
    g_qhi[o] = h0;     g_qlo[o]     = __float2half_rn(o0 - __half2float(h0));
    g_qhi[o + 1] = h1; g_qlo[o + 1] = __float2half_rn(o1 - __half2float(h1));
}

__global__ void rope_k_kernel(const float* __restrict__ fc, const float* __restrict__ fs)
{
    int idx = blockIdx.x * blockDim.x + threadIdx.x;    // BB*SS*HKV*64 pairs
    int p = idx & 63; int rest = idx >> 6;
    int kv = rest & 7; rest >>= 3;
    int s = rest & 511; int b = rest >> 9;
    float c  = fc[s * 64 + p];
    float si = fs[s * 64 + p];
    size_t so = ((size_t)(b * SS + s) * HKV + kv) * HD + 2 * p;
    size_t dd = ((size_t)(b * TT + STARTP + s) * HKV + kv) * HD + 2 * p;
    float a  = __half2float(g_kthi[so])     + __half2float(g_ktlo[so]);
    float bb = __half2float(g_kthi[so + 1]) + __half2float(g_ktlo[so + 1]);
    float o0 = a * c - bb * si, o1 = a * si + bb * c;
    __half h0 = __float2half_rn(o0), h1 = __float2half_rn(o1);
    g_khi[dd] = h0;     g_klo[dd]     = __float2half_rn(o0 - __half2float(h0));
    g_khi[dd + 1] = h1; g_klo[dd + 1] = __float2half_rn(o1 - __half2float(h1));
}

__global__ void cachek_kernel(const float* __restrict__ ck)
{
    int i = blockIdx.x * blockDim.x + threadIdx.x;      // BB*STARTP*HKV*HD
    int b = i >> 19;
    size_t d = (size_t)i + (size_t)b * (STARTP * HKV * HD);
    float v = ck[i];
    __half h = __float2half_rn(v);
    g_khi[d] = h;
    g_klo[d] = __float2half_rn(v - __half2float(h));
}

// V^T build: vT[b][kv][hd][t], from cache_v (t<512) or split v proj (t>=512)
__global__ void vT_build(const float* __restrict__ cv)
{
    int bkv = blockIdx.z; int b = bkv >> 3, kv = bkv & 7;
    int t0 = blockIdx.x * 32, hd0 = blockIdx.y * 32;
    __shared__ float tile[32][33];
    for (int i = threadIdx.y; i < 32; i += 8) {
        int t = t0 + i; int hd = hd0 + threadIdx.x;
        float v;
        if (t < STARTP) v = cv[(((size_t)b * STARTP + t) * HKV + kv) * HD + hd];
        else {
            size_t o = (((size_t)b * SS + (t - STARTP)) * HKV + kv) * HD + hd;
            v = __half2float(g_vthi[o]) + __half2float(g_vtlo[o]);
        }
        tile[i][threadIdx.x] = v;
    }
    __syncthreads();
    for (int i = threadIdx.y; i < 32; i += 8) {
        int hd = hd0 + i; int t = t0 + threadIdx.x;
        float v = tile[threadIdx.x][i];
        __half h = __float2half_rn(v);
        size_t o = ((size_t)bkv * HD + hd) * TT + t;
        g_vThi[o] = h;
        g_vTlo[o] = __float2half_rn(v - __half2float(h));
    }
}

__global__ __launch_bounds__(128) void softmax_kernel()
{
    int rI = blockIdx.x;             // (b*H+h)*S + s
    int s = rI & 511;
    int L = STARTP + 1 + s;
    const float* row = g_scores + (size_t)rI * TT;
    int tid = threadIdx.x;
    int lane = tid & 31, warp = tid >> 5;
    __shared__ float red[4];

    float v[8];
    float m = -INFINITY;
#pragma unroll
    for (int j = 0; j < 8; j++) {
        int t = j * 128 + tid;
        float x = (t < L) ? row[t] : -INFINITY;
        v[j] = x;
        m = fmaxf(m, x);
    }
#pragma unroll
    for (int o = 16; o > 0; o >>= 1) m = fmaxf(m, __shfl_xor_sync(0xffffffffu, m, o));
    if (lane == 0) red[warp] = m;
    __syncthreads();
    m = fmaxf(fmaxf(red[0], red[1]), fmaxf(red[2], red[3]));
    __syncthreads();

    float sum = 0.0f;
#pragma unroll
    for (int j = 0; j < 8; j++) {
        float e = expf(v[j] - m);
        v[j] = e;
        sum += e;
    }
#pragma unroll
    for (int o = 16; o > 0; o >>= 1) sum += __shfl_xor_sync(0xffffffffu, sum, o);
    if (lane == 0) red[warp] = sum;
    __syncthreads();
    sum = red[0] + red[1] + red[2] + red[3];
    float inv = 1.0f / sum;
#pragma unroll
    for (int j = 0; j < 8; j++) {
        int t = j * 128 + tid;
        float p = v[j] * inv;
        __half h = __float2half_rn(p);
        g_phi[(size_t)rI * TT + t] = h;
        g_plo[(size_t)rI * TT + t] = __float2half_rn(p - __half2float(h));
    }
}

// ---------------- launch -----------------------------------------------------
extern "C" void kernel_launch(void* const* d_in, const int* in_sizes, int n_in,
                              void* d_out, int out_size)
{
    const float* x  = (const float*)d_in[0];
    const float* wq = (const float*)d_in[1];
    const float* wk = (const float*)d_in[2];
    const float* wv = (const float*)d_in[3];
    const float* wo = (const float*)d_in[4];
    const float* fc = (const float*)d_in[5];
    const float* fs = (const float*)d_in[6];
    const float* ck = (const float*)d_in[7];
    const float* cv = (const float*)d_in[8];
    float* out = (float*)d_out;

    cudaFuncSetAttribute(tc_qkv,    cudaFuncAttributeMaxDynamicSharedMemorySize, DSMEM);
    cudaFuncSetAttribute(tc_wo,     cudaFuncAttributeMaxDynamicSharedMemorySize, DSMEM);
    cudaFuncSetAttribute(tc_scores, cudaFuncAttributeMaxDynamicSharedMemorySize, DSMEM);
    cudaFuncSetAttribute(tc_pv,     cudaFuncAttributeMaxDynamicSharedMemorySize, DSMEM);

    // 0) split all fp32 inputs to f16 hi/lo (one launch)
    split_all<<<8192, 256>>>(x, wq, wk, wv, wo);

    // 1) fused Q/K/V projections (split-f16 out)
    tc_qkv<<<dim3(48, 16), 256, DSMEM>>>();

    // 2) rope + KV assembly
    rope_q_kernel<<<(BB * SS * HH * 64) / 256, 256>>>(fc, fs);
    rope_k_kernel<<<(BB * SS * HKV * 64) / 256, 256>>>(fc, fs);
    cachek_kernel<<<(BB * STARTP * HKV * HD) / 256, 256>>>(ck);
    vT_build<<<dim3(TT / 32, HD / 32, BB * HKV), dim3(32, 8)>>>(cv);

    // 3) scores = scale * Q K^T
    tc_scores<<<dim3(TT / 128, SS / 128, BB * HH), 256, DSMEM>>>();

    // 4) causal softmax -> split-f16 probs
    softmax_kernel<<<BB * HH * SS, 128>>>();

    // 5) attn = P V -> split-f16
    tc_pv<<<dim3(1, SS / 128, BB * HH), 256, DSMEM>>>();

    // 6) output projection -> d_out (fp32)
    tc_wo<<<dim3(32, 16), 256, DSMEM>>>(out);
}

// round 6
// speedup vs baseline: 1.1955x; 1.1955x over previous
#include <cuda_runtime.h>
#include <cuda_fp16.h>
#include <math.h>
#include <stdint.h>

#define BB 4
#define SS 512
#define DD 4096
#define HH 32
#define HKV 8
#define HD 128
#define STARTP 512
#define TT 1024
#define MTOK (BB*SS)

// ---------------- scratch (static device globals) ----------------------------
__device__ float g_scores[(size_t)BB * HH * SS * TT];

__device__ __half g_xhi[(size_t)MTOK * DD],  g_xlo[(size_t)MTOK * DD];
__device__ __half g_wqhi[(size_t)DD * DD],   g_wqlo[(size_t)DD * DD];
__device__ __half g_wkhi[(size_t)HKV*HD*DD], g_wklo[(size_t)HKV*HD*DD];
__device__ __half g_wvhi[(size_t)HKV*HD*DD], g_wvlo[(size_t)HKV*HD*DD];
__device__ __half g_wohi[(size_t)DD * DD],   g_wolo[(size_t)DD * DD];
__device__ __half g_qhi[(size_t)MTOK * DD],  g_qlo[(size_t)MTOK * DD];
__device__ __half g_kthi[(size_t)MTOK*HKV*HD], g_ktlo[(size_t)MTOK*HKV*HD];
__device__ __half g_vthi[(size_t)MTOK*HKV*HD], g_vtlo[(size_t)MTOK*HKV*HD];
__device__ __half g_khi[(size_t)BB*TT*HKV*HD], g_klo[(size_t)BB*TT*HKV*HD];
__device__ __half g_vThi[(size_t)BB*HKV*HD*TT], g_vTlo[(size_t)BB*HKV*HD*TT];
__device__ __half g_phi[(size_t)BB*HH*SS*TT], g_plo[(size_t)BB*HH*SS*TT];
__device__ __half g_ahi[(size_t)MTOK * DD],  g_alo[(size_t)MTOK * DD];

// ---------------- PTX helpers ------------------------------------------------
__device__ __forceinline__ uint32_t smem_u32(const void* p){
    uint32_t a;
    asm("{ .reg .u64 t; cvta.to.shared.u64 t, %1; cvt.u32.u64 %0, t; }" : "=r"(a) : "l"(p));
    return a;
}
__device__ __forceinline__ void cpasync16(uint32_t d, const void* g){
    asm volatile("cp.async.cg.shared.global [%0], [%1], 16;" :: "r"(d), "l"(g));
}
__device__ __forceinline__ void ldsm4(uint32_t* x, uint32_t a){
    asm volatile("ldmatrix.sync.aligned.m8n8.x4.shared.b16 {%0,%1,%2,%3}, [%4];"
        : "=r"(x[0]), "=r"(x[1]), "=r"(x[2]), "=r"(x[3]) : "r"(a));
}
__device__ __forceinline__ void mma16816(float* d, const uint32_t* a, uint32_t b0, uint32_t b1){
    asm volatile("mma.sync.aligned.m16n8k16.row.col.f32.f16.f16.f32 "
        "{%0,%1,%2,%3}, {%4,%5,%6,%7}, {%8,%9}, {%0,%1,%2,%3};"
        : "+f"(d[0]), "+f"(d[1]), "+f"(d[2]), "+f"(d[3])
        : "r"(a[0]), "r"(a[1]), "r"(a[2]), "r"(a[3]), "r"(b0), "r"(b1));
}

// smem (halves): per buffer  Ah@0  Al@5120  Bh@10240  Bl@15360 ; pitch 40 halves
#define PITCH 40
#define ABYTES 10240
#define BUFBYTES 40960
#define DSMEM 81920

// ---------------- split-f16 HMMA GEMM core (R4 inner loop) -------------------
// C[M,N] = alpha * A * B^T ;  A[M,K] hi/lo (lda), B[N,K] hi/lo (ldb)
// A*B ~= Ah*Bh + Ah*Bl + Al*Bh.  EPI=0: fp32 C.  EPI=1: split-f16 Chi/Clo.
template<int EPI>
__device__ __forceinline__ void mma_core(
    const __half* __restrict__ Ahi, const __half* __restrict__ Alo, int lda,
    const __half* __restrict__ Bhi, const __half* __restrict__ Blo, int ldb,
    float* __restrict__ C, __half* __restrict__ Chi, __half* __restrict__ Clo, int ldc,
    int K, float alpha, int bm, int bn)
{
    extern __shared__ __half sm[];
    const uint32_t sbase = smem_u32(sm);
    const int tid  = threadIdx.x;
    const int lane = tid & 31, wid = tid >> 5;
    const int wm = (wid & 3) * 32;
    const int wn = (wid >> 2) * 64;

    float acc[2][8][4];
#pragma unroll
    for (int i = 0; i < 2; i++)
#pragma unroll
        for (int j = 0; j < 8; j++)
#pragma unroll
            for (int k = 0; k < 4; k++) acc[i][j][k] = 0.0f;

    const int q = lane >> 3, r = lane & 7;
    const uint32_t offA = (uint32_t)(((wm + (q & 1) * 8 + r) * PITCH + (q >> 1) * 8) * 2);
    const uint32_t offB = (uint32_t)(((wn + (q >> 1) * 8 + r) * PITCH + (q & 1) * 8) * 2);

    const int row0 = tid >> 2, seg0 = (tid & 3) * 8;
    const int row1 = (tid + 256) >> 2, seg1 = ((tid + 256) & 3) * 8;

    const int NC = K >> 5;

#define LOAD_CHUNK(c, buf) do {                                                  \
    uint32_t db = sbase + (buf) * BUFBYTES;                                      \
    const __half* a0 = Ahi + (size_t)(bm + row0) * lda + (c) * 32 + seg0;        \
    const __half* l0 = Alo + (size_t)(bm + row0) * lda + (c) * 32 + seg0;        \
    const __half* b0 = Bhi + (size_t)(bn + row0) * ldb + (c) * 32 + seg0;        \
    const __half* c0 = Blo + (size_t)(bn + row0) * ldb + (c) * 32 + seg0;        \
    uint32_t d0 = db + (uint32_t)(row0 * PITCH + seg0) * 2;                      \
    cpasync16(d0, a0);  cpasync16(d0 + ABYTES, l0);                              \
    cpasync16(d0 + 2*ABYTES, b0);  cpasync16(d0 + 3*ABYTES, c0);                 \
    const __half* a1 = Ahi + (size_t)(bm + row1) * lda + (c) * 32 + seg1;        \
    const __half* l1 = Alo + (size_t)(bm + row1) * lda + (c) * 32 + seg1;        \
    const __half* b1 = Bhi + (size_t)(bn + row1) * ldb + (c) * 32 + seg1;        \
    const __half* c1 = Blo + (size_t)(bn + row1) * ldb + (c) * 32 + seg1;        \
    uint32_t d1 = db + (uint32_t)(row1 * PITCH + seg1) * 2;                      \
    cpasync16(d1, a1);  cpasync16(d1 + ABYTES, l1);                              \
    cpasync16(d1 + 2*ABYTES, b1);  cpasync16(d1 + 3*ABYTES, c1);                 \
    asm volatile("cp.async.commit_group;" ::: "memory");                         \
} while (0)

    LOAD_CHUNK(0, 0);

    for (int c = 0; c < NC; ++c) {
        if (c + 1 < NC) {
            LOAD_CHUNK(c + 1, (c + 1) & 1);
            asm volatile("cp.async.wait_group 1;" ::: "memory");
        } else {
            asm volatile("cp.async.wait_group 0;" ::: "memory");
        }
        __syncthreads();

        uint32_t base = sbase + (c & 1) * BUFBYTES;
#pragma unroll
        for (int ks = 0; ks < 2; ks++) {
            uint32_t ah[2][4], al[2][4], bh[4][4], bl[4][4];
            const uint32_t kso = (uint32_t)(ks * 16 * 2);
#pragma unroll
            for (int mt = 0; mt < 2; mt++) {
                uint32_t o = base + offA + (uint32_t)(mt * 16 * PITCH * 2) + kso;
                ldsm4(ah[mt], o);
                ldsm4(al[mt], o + ABYTES);
            }
#pragma unroll
            for (int j = 0; j < 4; j++) {
                uint32_t o = base + 2 * ABYTES + offB + (uint32_t)(j * 16 * PITCH * 2) + kso;
                ldsm4(bh[j], o);
                ldsm4(bl[j], o + ABYTES);
            }
#pragma unroll
            for (int mt = 0; mt < 2; mt++)
#pragma unroll
                for (int nt = 0; nt < 8; nt++) {
                    const int j = nt >> 1, o = (nt & 1) * 2;
                    mma16816(acc[mt][nt], ah[mt], bh[j][o], bh[j][o + 1]);
                    mma16816(acc[mt][nt], ah[mt], bl[j][o], bl[j][o + 1]);
                    mma16816(acc[mt][nt], al[mt], bh[j][o], bh[j][o + 1]);
                }
        }
        __syncthreads();
    }
#undef LOAD_CHUNK

    const int er = bm + wm + (lane >> 2);
    const int ec = bn + wn + 2 * (lane & 3);
#pragma unroll
    for (int mt = 0; mt < 2; mt++)
#pragma unroll
        for (int nt = 0; nt < 8; nt++) {
            int rr = er + mt * 16;
            int cc = ec + nt * 8;
            float v0 = alpha * acc[mt][nt][0];
            float v1 = alpha * acc[mt][nt][1];
            float v2 = alpha * acc[mt][nt][2];
            float v3 = alpha * acc[mt][nt][3];
            if (EPI == 0) {
                *(float2*)(C + (size_t)rr * ldc + cc)       = make_float2(v0, v1);
                *(float2*)(C + (size_t)(rr + 8) * ldc + cc) = make_float2(v2, v3);
            } else {
                __half h0 = __float2half_rn(v0), h1 = __float2half_rn(v1);
                __half h2 = __float2half_rn(v2), h3 = __float2half_rn(v3);
                *(__half2*)(Chi + (size_t)rr * ldc + cc) = __halves2half2(h0, h1);
                *(__half2*)(Clo + (size_t)rr * ldc + cc) = __halves2half2(
                    __float2half_rn(v0 - __half2float(h0)), __float2half_rn(v1 - __half2float(h1)));
                *(__half2*)(Chi + (size_t)(rr + 8) * ldc + cc) = __halves2half2(h2, h3);
                *(__half2*)(Clo + (size_t)(rr + 8) * ldc + cc) = __halves2half2(
                    __float2half_rn(v2 - __half2float(h2)), __float2half_rn(v3 - __half2float(h3)));
            }
        }
}

// fused QKV projection: blockIdx.x selects weight/output
__global__ __launch_bounds__(256, 1) void tc_qkv()
{
    int j = blockIdx.x;
    int bm = blockIdx.y * 128;
    if (j < 32) {
        mma_core<1>(g_xhi, g_xlo, DD, g_wqhi, g_wqlo, DD,
                    nullptr, g_qhi, g_qlo, DD, DD, 1.0f, bm, j * 128);
    } else if (j < 40) {
        mma_core<1>(g_xhi, g_xlo, DD, g_wkhi, g_wklo, DD,
                    nullptr, g_kthi, g_ktlo, HKV * HD, DD, 1.0f, bm, (j - 32) * 128);
    } else {
        mma_core<1>(g_xhi, g_xlo, DD, g_wvhi, g_wvlo, DD,
                    nullptr, g_vthi, g_vtlo, HKV * HD, DD, 1.0f, bm, (j - 40) * 128);
    }
}

__global__ __launch_bounds__(256, 1) void tc_wo(float* __restrict__ out)
{
    mma_core<0>(g_ahi, g_alo, DD, g_wohi, g_wolo, DD,
                out, nullptr, nullptr, DD, DD, 1.0f, blockIdx.y * 128, blockIdx.x * 128);
}

__global__ __launch_bounds__(256, 1) void tc_scores()
{
    // causal skip: tile fully masked iff bn >= bm + 5 (t_min > s_max + 512)
    if ((int)blockIdx.x >= (int)blockIdx.y + 5) return;
    int z = blockIdx.z; int b = z >> 5, h = z & 31, kv = h >> 2;
    size_t ao = (size_t)b * SS * DD + (size_t)h * HD;
    size_t bo = ((size_t)b * TT * HKV + kv) * HD;
    mma_core<0>(g_qhi + ao, g_qlo + ao, DD, g_khi + bo, g_klo + bo, HKV * HD,
                g_scores + (size_t)z * SS * TT, nullptr, nullptr, TT, HD,
                0.08838834764831843f, blockIdx.y * 128, blockIdx.x * 128);
}

__global__ __launch_bounds__(256, 1) void tc_pv()
{
    int z = blockIdx.z; int b = z >> 5, h = z & 31, kv = h >> 2;
    size_t ao = (size_t)z * SS * TT;
    size_t bo = ((size_t)(b * HKV + kv) * HD) * TT;
    size_t co = ((size_t)b * SS * HH + h) * HD;
    // P[s,t] = 0 exactly for t > 512+s: truncate K to 640+128*bm (exact)
    int Keff = 640 + 128 * blockIdx.y;
    mma_core<1>(g_phi + ao, g_plo + ao, TT, g_vThi + bo, g_vTlo + bo, TT,
                nullptr, g_ahi + co, g_alo + co, DD, Keff, 1.0f, blockIdx.y * 128, 0);
}

// ---------------- elementwise / setup ----------------------------------------
#define NX  (MTOK * DD)
#define NWQ (DD * DD)
#define NWK (HKV * HD * DD)
#define NTOT (NX + NWQ + 2 * NWK + NWQ)

__global__ void split_all(const float* __restrict__ x,  const float* __restrict__ wq,
                          const float* __restrict__ wk, const float* __restrict__ wv,
                          const float* __restrict__ wo)
{
    for (int i = blockIdx.x * blockDim.x + threadIdx.x; i < NTOT; i += gridDim.x * blockDim.x) {
        const float* src; __half *hi, *lo; int o = i;
        if (o < NX)                 { src = x;  hi = g_xhi;  lo = g_xlo; }
        else if ((o -= NX)  < NWQ)  { src = wq; hi = g_wqhi; lo = g_wqlo; }
        else if ((o -= NWQ) < NWK)  { src = wk; hi = g_wkhi; lo = g_wklo; }
        else if ((o -= NWK) < NWK)  { src = wv; hi = g_wvhi; lo = g_wvlo; }
        else  { o -= NWK;             src = wo; hi = g_wohi; lo = g_wolo; }
        float v = src[o];
        __half h = __float2half_rn(v);
        hi[o] = h;
        lo[o] = __float2half_rn(v - __half2float(h));
    }
}

__global__ void rope_q_kernel(const float* __restrict__ fc, const float* __restrict__ fs)
{
    int idx = blockIdx.x * blockDim.x + threadIdx.x;    // BB*SS*HH*64 pairs
    int p = idx & 63; int rest = idx >> 6;
    int h = rest & 31; rest >>= 5;
    int s = rest & 511; int b = rest >> 9;
    float c  = fc[s * 64 + p];
    float si = fs[s * 64 + p];
    size_t o = ((size_t)(b * SS + s) * HH + h) * HD + 2 * p;
    float a  = __half2float(g_qhi[o])     + __half2float(g_qlo[o]);
    float bb = __half2float(g_qhi[o + 1]) + __half2float(g_qlo[o + 1]);
    float o0 = a * c - bb * si, o1 = a * si + bb * c;
    __half h0 = __float2half_rn(o0), h1 = __float2half_rn(o1);
    g_qhi[o] = h0;     g_qlo[o]     = __float2half_rn(o0 - __half2float(h0));
    g_qhi[o + 1] = h1; g_qlo[o + 1] = __float2half_rn(o1 - __half2float(h1));
}

__global__ void rope_k_kernel(const float* __restrict__ fc, const float* __restrict__ fs)
{
    int idx = blockIdx.x * blockDim.x + threadIdx.x;    // BB*SS*HKV*64 pairs
    int p = idx & 63; int rest = idx >> 6;
    int kv = rest & 7; rest >>= 3;
    int s = rest & 511; int b = rest >> 9;
    float c  = fc[s * 64 + p];
    float si = fs[s * 64 + p];
    size_t so = ((size_t)(b * SS + s) * HKV + kv) * HD + 2 * p;
    size_t dd = ((size_t)(b * TT + STARTP + s) * HKV + kv) * HD + 2 * p;
    float a  = __half2float(g_kthi[so])     + __half2float(g_ktlo[so]);
    float bb = __half2float(g_kthi[so + 1]) + __half2float(g_ktlo[so + 1]);
    float o0 = a * c - bb * si, o1 = a * si + bb * c;
    __half h0 = __float2half_rn(o0), h1 = __float2half_rn(o1);
    g_khi[dd] = h0;     g_klo[dd]     = __float2half_rn(o0 - __half2float(h0));
    g_khi[dd + 1] = h1; g_klo[dd + 1] = __float2half_rn(o1 - __half2float(h1));
}

__global__ void cachek_kernel(const float* __restrict__ ck)
{
    int i = blockIdx.x * blockDim.x + threadIdx.x;      // BB*STARTP*HKV*HD
    int b = i >> 19;
    size_t d = (size_t)i + (size_t)b * (STARTP * HKV * HD);
    float v = ck[i];
    __half h = __float2half_rn(v);
    g_khi[d] = h;
    g_klo[d] = __float2half_rn(v - __half2float(h));
}

// V^T build: vT[b][kv][hd][t], from cache_v (t<512) or split v proj (t>=512)
__global__ void vT_build(const float* __restrict__ cv)
{
    int bkv = blockIdx.z; int b = bkv >> 3, kv = bkv & 7;
    int t0 = blockIdx.x * 32, hd0 = blockIdx.y * 32;
    __shared__ float tile[32][33];
    for (int i = threadIdx.y; i < 32; i += 8) {
        int t = t0 + i; int hd = hd0 + threadIdx.x;
        float v;
        if (t < STARTP) v = cv[(((size_t)b * STARTP + t) * HKV + kv) * HD + hd];
        else {
            size_t o = (((size_t)b * SS + (t - STARTP)) * HKV + kv) * HD + hd;
            v = __half2float(g_vthi[o]) + __half2float(g_vtlo[o]);
        }
        tile[i][threadIdx.x] = v;
    }
    __syncthreads();
    for (int i = threadIdx.y; i < 32; i += 8) {
        int hd = hd0 + i; int t = t0 + threadIdx.x;
        float v = tile[threadIdx.x][i];
        __half h = __float2half_rn(v);
        size_t o = ((size_t)bkv * HD + hd) * TT + t;
        g_vThi[o] = h;
        g_vTlo[o] = __float2half_rn(v - __half2float(h));
    }
}

__global__ __launch_bounds__(128) void softmax_kernel()
{
    int rI = blockIdx.x;             // (b*H+h)*S + s
    int s = rI & 511;
    int L = STARTP + 1 + s;
    const float* row = g_scores + (size_t)rI * TT;
    int tid = threadIdx.x;
    int lane = tid & 31, warp = tid >> 5;
    __shared__ float red[4];

    float v[8];
    float m = -INFINITY;
#pragma unroll
    for (int j = 0; j < 8; j++) {
        int t = j * 128 + tid;
        float x = (t < L) ? row[t] : -INFINITY;
        v[j] = x;
        m = fmaxf(m, x);
    }
#pragma unroll
    for (int o = 16; o > 0; o >>= 1) m = fmaxf(m, __shfl_xor_sync(0xffffffffu, m, o));
    if (lane == 0) red[warp] = m;
    __syncthreads();
    m = fmaxf(fmaxf(red[0], red[1]), fmaxf(red[2], red[3]));
    __syncthreads();

    float sum = 0.0f;
#pragma unroll
    for (int j = 0; j < 8; j++) {
        float e = expf(v[j] - m);
        v[j] = e;
        sum += e;
    }
#pragma unroll
    for (int o = 16; o > 0; o >>= 1) sum += __shfl_xor_sync(0xffffffffu, sum, o);
    if (lane == 0) red[warp] = sum;
    __syncthreads();
    sum = red[0] + red[1] + red[2] + red[3];
    float inv = 1.0f / sum;
#pragma unroll
    for (int j = 0; j < 8; j++) {
        int t = j * 128 + tid;
        float p = v[j] * inv;
        __half h = __float2half_rn(p);
        g_phi[(size_t)rI * TT + t] = h;
        g_plo[(size_t)rI * TT + t] = __float2half_rn(p - __half2float(h));
    }
}

// ---------------- launch -----------------------------------------------------
extern "C" void kernel_launch(void* const* d_in, const int* in_sizes, int n_in,
                              void* d_out, int out_size)
{
    const float* x  = (const float*)d_in[0];
    const float* wq = (const float*)d_in[1];
    const float* wk = (const float*)d_in[2];
    const float* wv = (const float*)d_in[3];
    const float* wo = (const float*)d_in[4];
    const float* fc = (const float*)d_in[5];
    const float* fs = (const float*)d_in[6];
    const float* ck = (const float*)d_in[7];
    const float* cv = (const float*)d_in[8];
    float* out = (float*)d_out;

    cudaFuncSetAttribute(tc_qkv,    cudaFuncAttributeMaxDynamicSharedMemorySize, DSMEM);
    cudaFuncSetAttribute(tc_wo,     cudaFuncAttributeMaxDynamicSharedMemorySize, DSMEM);
    cudaFuncSetAttribute(tc_scores, cudaFuncAttributeMaxDynamicSharedMemorySize, DSMEM);
    cudaFuncSetAttribute(tc_pv,     cudaFuncAttributeMaxDynamicSharedMemorySize, DSMEM);

    // 0) split all fp32 inputs to f16 hi/lo (one launch)
    split_all<<<8192, 256>>>(x, wq, wk, wv, wo);

    // 1) fused Q/K/V projections (split-f16 out)
    tc_qkv<<<dim3(48, 16), 256, DSMEM>>>();

    // 2) rope + KV assembly
    rope_q_kernel<<<(BB * SS * HH * 64) / 256, 256>>>(fc, fs);
    rope_k_kernel<<<(BB * SS * HKV * 64) / 256, 256>>>(fc, fs);
    cachek_kernel<<<(BB * STARTP * HKV * HD) / 256, 256>>>(ck);
    vT_build<<<dim3(TT / 32, HD / 32, BB * HKV), dim3(32, 8)>>>(cv);

    // 3) scores = scale * Q K^T  (causal tiles skipped inside)
    tc_scores<<<dim3(TT / 128, SS / 128, BB * HH), 256, DSMEM>>>();

    // 4) causal softmax -> split-f16 probs
    softmax_kernel<<<BB * HH * SS, 128>>>();

    // 5) attn = P V -> split-f16 (K truncated per s-block)
    tc_pv<<<dim3(1, SS / 128, BB * HH), 256, DSMEM>>>();

    // 6) output projection -> d_out (fp32)
    tc_wo<<<dim3(32, 16), 256, DSMEM>>>(out);
}

// round 8
// speedup vs baseline: 1.2590x; 1.0530x over previous
#include <cuda_runtime.h>
#include <cuda_fp16.h>
#include <math.h>
#include <stdint.h>

#define BB 4
#define SS 512
#define DD 4096
#define HH 32
#define HKV 8
#define HD 128
#define STARTP 512
#define TT 1024
#define MTOK (BB*SS)

// ---------------- scratch (static device globals) ----------------------------
__device__ __half g_xhi[(size_t)MTOK * DD],  g_xlo[(size_t)MTOK * DD];
__device__ __half g_wqhi[(size_t)DD * DD],   g_wqlo[(size_t)DD * DD];
__device__ __half g_wkhi[(size_t)HKV*HD*DD], g_wklo[(size_t)HKV*HD*DD];
__device__ __half g_wvhi[(size_t)HKV*HD*DD], g_wvlo[(size_t)HKV*HD*DD];
__device__ __half g_wohi[(size_t)DD * DD],   g_wolo[(size_t)DD * DD];
__device__ __half g_qhi[(size_t)MTOK * DD],  g_qlo[(size_t)MTOK * DD];
__device__ __half g_kthi[(size_t)MTOK*HKV*HD], g_ktlo[(size_t)MTOK*HKV*HD];
__device__ __half g_vthi[(size_t)MTOK*HKV*HD], g_vtlo[(size_t)MTOK*HKV*HD];
__device__ __half g_khi[(size_t)BB*TT*HKV*HD], g_klo[(size_t)BB*TT*HKV*HD];
__device__ __half g_vThi[(size_t)BB*HKV*HD*TT], g_vTlo[(size_t)BB*HKV*HD*TT];
__device__ __half g_ahi[(size_t)MTOK * DD],  g_alo[(size_t)MTOK * DD];

// ---------------- PTX helpers ------------------------------------------------
__device__ __forceinline__ uint32_t smem_u32(const void* p){
    uint32_t a;
    asm("{ .reg .u64 t; cvta.to.shared.u64 t, %1; cvt.u32.u64 %0, t; }" : "=r"(a) : "l"(p));
    return a;
}
__device__ __forceinline__ void cpasync16(uint32_t d, const void* g){
    asm volatile("cp.async.cg.shared.global [%0], [%1], 16;" :: "r"(d), "l"(g));
}
__device__ __forceinline__ void ldsm4(uint32_t* x, uint32_t a){
    asm volatile("ldmatrix.sync.aligned.m8n8.x4.shared.b16 {%0,%1,%2,%3}, [%4];"
        : "=r"(x[0]), "=r"(x[1]), "=r"(x[2]), "=r"(x[3]) : "r"(a));
}
__device__ __forceinline__ void mma16816(float* d, const uint32_t* a, uint32_t b0, uint32_t b1){
    asm volatile("mma.sync.aligned.m16n8k16.row.col.f32.f16.f16.f32 "
        "{%0,%1,%2,%3}, {%4,%5,%6,%7}, {%8,%9}, {%0,%1,%2,%3};"
        : "+f"(d[0]), "+f"(d[1]), "+f"(d[2]), "+f"(d[3])
        : "r"(a[0]), "r"(a[1]), "r"(a[2]), "r"(a[3]), "r"(b0), "r"(b1));
}
__device__ __forceinline__ uint32_t packh2(__half x, __half y){
    __half2 t = __halves2half2(x, y);
    return *(uint32_t*)&t;
}

// smem (halves): per buffer  Ah@0  Al@5120  Bh@10240  Bl@15360 ; pitch 40 halves
#define PITCH 40
#define ABYTES 10240
#define BUFBYTES 40960
#define DSMEM 81920

// ---------------- split-f16 HMMA GEMM core (R4 inner loop) -------------------
template<int EPI>
__device__ __forceinline__ void mma_core(
    const __half* __restrict__ Ahi, const __half* __restrict__ Alo, int lda,
    const __half* __restrict__ Bhi, const __half* __restrict__ Blo, int ldb,
    float* __restrict__ C, __half* __restrict__ Chi, __half* __restrict__ Clo, int ldc,
    int K, float alpha, int bm, int bn)
{
    extern __shared__ __half sm[];
    const uint32_t sbase = smem_u32(sm);
    const int tid  = threadIdx.x;
    const int lane = tid & 31, wid = tid >> 5;
    const int wm = (wid & 3) * 32;
    const int wn = (wid >> 2) * 64;

    float acc[2][8][4];
#pragma unroll
    for (int i = 0; i < 2; i++)
#pragma unroll
        for (int j = 0; j < 8; j++)
#pragma unroll
            for (int k = 0; k < 4; k++) acc[i][j][k] = 0.0f;

    const int q = lane >> 3, r = lane & 7;
    const uint32_t offA = (uint32_t)(((wm + (q & 1) * 8 + r) * PITCH + (q >> 1) * 8) * 2);
    const uint32_t offB = (uint32_t)(((wn + (q >> 1) * 8 + r) * PITCH + (q & 1) * 8) * 2);

    const int row0 = tid >> 2, seg0 = (tid & 3) * 8;
    const int row1 = (tid + 256) >> 2, seg1 = ((tid + 256) & 3) * 8;

    const int NC = K >> 5;

#define LOAD_CHUNK(c, buf) do {                                                  \
    uint32_t db = sbase + (buf) * BUFBYTES;                                      \
    const __half* a0 = Ahi + (size_t)(bm + row0) * lda + (c) * 32 + seg0;        \
    const __half* l0 = Alo + (size_t)(bm + row0) * lda + (c) * 32 + seg0;        \
    const __half* b0 = Bhi + (size_t)(bn + row0) * ldb + (c) * 32 + seg0;        \
    const __half* c0 = Blo + (size_t)(bn + row0) * ldb + (c) * 32 + seg0;        \
    uint32_t d0 = db + (uint32_t)(row0 * PITCH + seg0) * 2;                      \
    cpasync16(d0, a0);  cpasync16(d0 + ABYTES, l0);                              \
    cpasync16(d0 + 2*ABYTES, b0);  cpasync16(d0 + 3*ABYTES, c0);                 \
    const __half* a1 = Ahi + (size_t)(bm + row1) * lda + (c) * 32 + seg1;        \
    const __half* l1 = Alo + (size_t)(bm + row1) * lda + (c) * 32 + seg1;        \
    const __half* b1 = Bhi + (size_t)(bn + row1) * ldb + (c) * 32 + seg1;        \
    const __half* c1 = Blo + (size_t)(bn + row1) * ldb + (c) * 32 + seg1;        \
    uint32_t d1 = db + (uint32_t)(row1 * PITCH + seg1) * 2;                      \
    cpasync16(d1, a1);  cpasync16(d1 + ABYTES, l1);                              \
    cpasync16(d1 + 2*ABYTES, b1);  cpasync16(d1 + 3*ABYTES, c1);                 \
    asm volatile("cp.async.commit_group;" ::: "memory");                         \
} while (0)

    LOAD_CHUNK(0, 0);

    for (int c = 0; c < NC; ++c) {
        if (c + 1 < NC) {
            LOAD_CHUNK(c + 1, (c + 1) & 1);
            asm volatile("cp.async.wait_group 1;" ::: "memory");
        } else {
            asm volatile("cp.async.wait_group 0;" ::: "memory");
        }
        __syncthreads();

        uint32_t base = sbase + (c & 1) * BUFBYTES;
#pragma unroll
        for (int ks = 0; ks < 2; ks++) {
            uint32_t ah[2][4], al[2][4], bh[4][4], bl[4][4];
            const uint32_t kso = (uint32_t)(ks * 16 * 2);
#pragma unroll
            for (int mt = 0; mt < 2; mt++) {
                uint32_t o = base + offA + (uint32_t)(mt * 16 * PITCH * 2) + kso;
                ldsm4(ah[mt], o);
                ldsm4(al[mt], o + ABYTES);
            }
#pragma unroll
            for (int j = 0; j < 4; j++) {
                uint32_t o = base + 2 * ABYTES + offB + (uint32_t)(j * 16 * PITCH * 2) + kso;
                ldsm4(bh[j], o);
                ldsm4(bl[j], o + ABYTES);
            }
#pragma unroll
            for (int mt = 0; mt < 2; mt++)
#pragma unroll
                for (int nt = 0; nt < 8; nt++) {
                    const int j = nt >> 1, o = (nt & 1) * 2;
                    mma16816(acc[mt][nt], ah[mt], bh[j][o], bh[j][o + 1]);
                    mma16816(acc[mt][nt], ah[mt], bl[j][o], bl[j][o + 1]);
                    mma16816(acc[mt][nt], al[mt], bh[j][o], bh[j][o + 1]);
                }
        }
        __syncthreads();
    }
#undef LOAD_CHUNK

    const int er = bm + wm + (lane >> 2);
    const int ec = bn + wn + 2 * (lane & 3);
#pragma unroll
    for (int mt = 0; mt < 2; mt++)
#pragma unroll
        for (int nt = 0; nt < 8; nt++) {
            int rr = er + mt * 16;
            int cc = ec + nt * 8;
            float v0 = alpha * acc[mt][nt][0];
            float v1 = alpha * acc[mt][nt][1];
            float v2 = alpha * acc[mt][nt][2];
            float v3 = alpha * acc[mt][nt][3];
            if (EPI == 0) {
                *(float2*)(C + (size_t)rr * ldc + cc)       = make_float2(v0, v1);
                *(float2*)(C + (size_t)(rr + 8) * ldc + cc) = make_float2(v2, v3);
            } else {
                __half h0 = __float2half_rn(v0), h1 = __float2half_rn(v1);
                __half h2 = __float2half_rn(v2), h3 = __float2half_rn(v3);
                *(__half2*)(Chi + (size_t)rr * ldc + cc) = __halves2half2(h0, h1);
                *(__half2*)(Clo + (size_t)rr * ldc + cc) = __halves2half2(
                    __float2half_rn(v0 - __half2float(h0)), __float2half_rn(v1 - __half2float(h1)));
                *(__half2*)(Chi + (size_t)(rr + 8) * ldc + cc) = __halves2half2(h2, h3);
                *(__half2*)(Clo + (size_t)(rr + 8) * ldc + cc) = __halves2half2(
                    __float2half_rn(v2 - __half2float(h2)), __float2half_rn(v3 - __half2float(h3)));
            }
        }
}

__global__ __launch_bounds__(256, 1) void tc_qkv()
{
    int j = blockIdx.x;
    int bm = blockIdx.y * 128;
    if (j < 32) {
        mma_core<1>(g_xhi, g_xlo, DD, g_wqhi, g_wqlo, DD,
                    nullptr, g_qhi, g_qlo, DD, DD, 1.0f, bm, j * 128);
    } else if (j < 40) {
        mma_core<1>(g_xhi, g_xlo, DD, g_wkhi, g_wklo, DD,
                    nullptr, g_kthi, g_ktlo, HKV * HD, DD, 1.0f, bm, (j - 32) * 128);
    } else {
        mma_core<1>(g_xhi, g_xlo, DD, g_wvhi, g_wvlo, DD,
                    nullptr, g_vthi, g_vtlo, HKV * HD, DD, 1.0f, bm, (j - 40) * 128);
    }
}

__global__ __launch_bounds__(256, 1) void tc_wo(float* __restrict__ out)
{
    mma_core<0>(g_ahi, g_alo, DD, g_wohi, g_wolo, DD,
                out, nullptr, nullptr, DD, DD, 1.0f, blockIdx.y * 128, blockIdx.x * 128);
}

// ---------------- flash attention (scores+softmax+PV fused) ------------------
// grid (4 s-blocks, 128 z); 256 thr; warp owns 16 s-rows.
// smem planes 128x136 halves (pitch 272 B): Qhi Qlo Khi Klo Vhi Vlo
#define PFB 272
#define SQHI 0
#define SQLO 34816
#define SKHI 69632
#define SKLO 104448
#define SVHI 139264
#define SVLO 174080
#define SMEMF 208896

__global__ __launch_bounds__(256, 1) void tc_flash()
{
    const int i = blockIdx.x;
    const int z = blockIdx.y;
    const int b = z >> 5, h = z & 31, kv = h >> 2;
    extern __shared__ __half sm[];
    const uint32_t sb = smem_u32(sm);
    const int tid = threadIdx.x, lane = tid & 31, wid = tid >> 5;
    const int s0 = i * 128;
    const int NT = i + 5;          // t-tiles: 0..i+3 full, i+4 masked

    // prologue: load Q, K(0), V(0)  — 2048 x 16B per plane
#pragma unroll
    for (int it = 0; it < 8; it++) {
        int id = tid + it * 256;
        int row = id >> 4, cs = (id & 15) * 8;   // cs in halves
        uint32_t d = sb + row * PFB + cs * 2;
        size_t qoff = (size_t)(b * SS + s0 + row) * DD + h * HD + cs;
        cpasync16(d + SQHI, g_qhi + qoff);
        cpasync16(d + SQLO, g_qlo + qoff);
        size_t koff = ((size_t)(b * TT + row) * HKV + kv) * HD + cs;
        cpasync16(d + SKHI, g_khi + koff);
        cpasync16(d + SKLO, g_klo + koff);
        size_t voff = ((size_t)(b * HKV + kv) * HD + row) * TT + cs;
        cpasync16(d + SVHI, g_vThi + voff);
        cpasync16(d + SVLO, g_vTlo + voff);
    }
    asm volatile("cp.async.commit_group;" ::: "memory");

    float m0 = -INFINITY, m1 = -INFINITY, l0 = 0.0f, l1 = 0.0f;
    float oacc[16][4];
#pragma unroll
    for (int n = 0; n < 16; n++)
#pragma unroll
        for (int c = 0; c < 4; c++) oacc[n][c] = 0.0f;

    const int qq = lane >> 3, rr = lane & 7;
    const uint32_t offQ  = (uint32_t)((wid * 16 + (qq & 1) * 8 + rr) * PFB + (qq >> 1) * 16);
    const uint32_t offBn = (uint32_t)(((qq >> 1) * 8 + rr) * PFB + (qq & 1) * 16);

    for (int j = 0; j < NT; j++) {
        asm volatile("cp.async.wait_group 0;" ::: "memory");
        __syncthreads();

        // ---- S = Q K^T ----
        float sacc[16][4];
#pragma unroll
        for (int n = 0; n < 16; n++)
#pragma unroll
            for (int c = 0; c < 4; c++) sacc[n][c] = 0.0f;

#pragma unroll
        for (int ks = 0; ks < 8; ks++) {
            uint32_t ah[4], al[4];
            ldsm4(ah, sb + SQHI + offQ + ks * 32);
            ldsm4(al, sb + SQLO + offQ + ks * 32);
#pragma unroll
            for (int j2 = 0; j2 < 8; j2++) {
                uint32_t bh[4], bl[4];
                uint32_t o = sb + SKHI + (uint32_t)(j2 * 16 * PFB) + offBn + ks * 32;
                ldsm4(bh, o);
                ldsm4(bl, o + (SKLO - SKHI));
                mma16816(sacc[2*j2],   ah, bh[0], bh[1]);
                mma16816(sacc[2*j2+1], ah, bh[2], bh[3]);
                mma16816(sacc[2*j2],   ah, bl[0], bl[1]);
                mma16816(sacc[2*j2+1], ah, bl[2], bl[3]);
                mma16816(sacc[2*j2],   al, bh[0], bh[1]);
                mma16816(sacc[2*j2+1], al, bh[2], bh[3]);
            }
        }
        __syncthreads();
        // prefetch K(j+1) (overlaps softmax + PV)
        if (j + 1 < NT) {
#pragma unroll
            for (int it = 0; it < 8; it++) {
                int id = tid + it * 256;
                int row = id >> 4, cs = (id & 15) * 8;
                uint32_t d = sb + row * PFB + cs * 2;
                size_t koff = ((size_t)(b * TT + (j + 1) * 128 + row) * HKV + kv) * HD + cs;
                cpasync16(d + SKHI, g_khi + koff);
                cpasync16(d + SKLO, g_klo + koff);
            }
            asm volatile("cp.async.commit_group;" ::: "memory");
        }

        // ---- scale + causal mask (last tile only) ----
        const float scale = 0.08838834764831843f;
#pragma unroll
        for (int n = 0; n < 16; n++)
#pragma unroll
            for (int c = 0; c < 4; c++) sacc[n][c] *= scale;

        if (j == NT - 1) {
            int r0 = wid * 16 + (lane >> 2);
            int tb = 2 * (lane & 3);
#pragma unroll
            for (int n = 0; n < 16; n++) {
                int tc = n * 8 + tb;
                if (tc     > r0)     sacc[n][0] = -INFINITY;
                if (tc + 1 > r0)     sacc[n][1] = -INFINITY;
                if (tc     > r0 + 8) sacc[n][2] = -INFINITY;
                if (tc + 1 > r0 + 8) sacc[n][3] = -INFINITY;
            }
        }

        // ---- online softmax ----
        float mx0 = -INFINITY, mx1 = -INFINITY;
#pragma unroll
        for (int n = 0; n < 16; n++) {
            mx0 = fmaxf(mx0, fmaxf(sacc[n][0], sacc[n][1]));
            mx1 = fmaxf(mx1, fmaxf(sacc[n][2], sacc[n][3]));
        }
        mx0 = fmaxf(mx0, __shfl_xor_sync(0xffffffffu, mx0, 1));
        mx0 = fmaxf(mx0, __shfl_xor_sync(0xffffffffu, mx0, 2));
        mx1 = fmaxf(mx1, __shfl_xor_sync(0xffffffffu, mx1, 1));
        mx1 = fmaxf(mx1, __shfl_xor_sync(0xffffffffu, mx1, 2));
        float mn0 = fmaxf(m0, mx0), mn1 = fmaxf(m1, mx1);
        float e0 = expf(m0 - mn0), e1 = expf(m1 - mn1);
        m0 = mn0; m1 = mn1;

        float sum0 = 0.0f, sum1 = 0.0f;
#pragma unroll
        for (int n = 0; n < 16; n++) {
            float p0 = expf(sacc[n][0] - mn0); sacc[n][0] = p0; sum0 += p0;
            float p1 = expf(sacc[n][1] - mn0); sacc[n][1] = p1; sum0 += p1;
            float p2 = expf(sacc[n][2] - mn1); sacc[n][2] = p2; sum1 += p2;
            float p3 = expf(sacc[n][3] - mn1); sacc[n][3] = p3; sum1 += p3;
        }
        sum0 += __shfl_xor_sync(0xffffffffu, sum0, 1);
        sum0 += __shfl_xor_sync(0xffffffffu, sum0, 2);
        sum1 += __shfl_xor_sync(0xffffffffu, sum1, 1);
        sum1 += __shfl_xor_sync(0xffffffffu, sum1, 2);
        l0 = l0 * e0 + sum0;
        l1 = l1 * e1 + sum1;
#pragma unroll
        for (int n = 0; n < 16; n++) {
            oacc[n][0] *= e0; oacc[n][1] *= e0;
            oacc[n][2] *= e1; oacc[n][3] *= e1;
        }

        // ---- O += P V ----
#pragma unroll
        for (int ks = 0; ks < 8; ks++) {
            float p00 = sacc[2*ks][0],   p01 = sacc[2*ks][1];
            float p02 = sacc[2*ks][2],   p03 = sacc[2*ks][3];
            float p10 = sacc[2*ks+1][0], p11 = sacc[2*ks+1][1];
            float p12 = sacc[2*ks+1][2], p13 = sacc[2*ks+1][3];
            __half h00 = __float2half_rn(p00), h01 = __float2half_rn(p01);
            __half h02 = __float2half_rn(p02), h03 = __float2half_rn(p03);
            __half h10 = __float2half_rn(p10), h11 = __float2half_rn(p11);
            __half h12 = __float2half_rn(p12), h13 = __float2half_rn(p13);
            uint32_t a_h[4], a_l[4];
            a_h[0] = packh2(h00, h01);
            a_h[1] = packh2(h02, h03);
            a_h[2] = packh2(h10, h11);
            a_h[3] = packh2(h12, h13);
            a_l[0] = packh2(__float2half_rn(p00 - __half2float(h00)), __float2half_rn(p01 - __half2float(h01)));
            a_l[1] = packh2(__float2half_rn(p02 - __half2float(h02)), __float2half_rn(p03 - __half2float(h03)));
            a_l[2] = packh2(__float2half_rn(p10 - __half2float(h10)), __float2half_rn(p11 - __half2float(h11)));
            a_l[3] = packh2(__float2half_rn(p12 - __half2float(h12)), __float2half_rn(p13 - __half2float(h13)));
#pragma unroll
            for (int j2 = 0; j2 < 8; j2++) {
                uint32_t bh[4], bl[4];
                uint32_t o = sb + SVHI + (uint32_t)(j2 * 16 * PFB) + offBn + ks * 32;
                ldsm4(bh, o);
                ldsm4(bl, o + (SVLO - SVHI));
                mma16816(oacc[2*j2],   a_h, bh[0], bh[1]);
                mma16816(oacc[2*j2+1], a_h, bh[2], bh[3]);
                mma16816(oacc[2*j2],   a_l, bh[0], bh[1]);
                mma16816(oacc[2*j2+1], a_l, bh[2], bh[3]);
                mma16816(oacc[2*j2],   a_h, bl[0], bl[1]);
                mma16816(oacc[2*j2+1], a_h, bl[2], bl[3]);
            }
        }
        __syncthreads();
        // prefetch V(j+1)
        if (j + 1 < NT) {
#pragma unroll
            for (int it = 0; it < 8; it++) {
                int id = tid + it * 256;
                int row = id >> 4, cs = (id & 15) * 8;
                uint32_t d = sb + row * PFB + cs * 2;
                size_t voff = ((size_t)(b * HKV + kv) * HD + row) * TT + (j + 1) * 128 + cs;
                cpasync16(d + SVHI, g_vThi + voff);
                cpasync16(d + SVLO, g_vTlo + voff);
            }
            asm volatile("cp.async.commit_group;" ::: "memory");
        }
    }

    // ---- normalize + split-f16 store ----
    float i0 = 1.0f / l0, i1 = 1.0f / l1;
    int grow = b * SS + s0 + wid * 16 + (lane >> 2);
    int gcol = h * HD + 2 * (lane & 3);
#pragma unroll
    for (int n = 0; n < 16; n++) {
        int cc = gcol + n * 8;
        float v0 = oacc[n][0] * i0, v1 = oacc[n][1] * i0;
        float v2 = oacc[n][2] * i1, v3 = oacc[n][3] * i1;
        __half h0 = __float2half_rn(v0), h1 = __float2half_rn(v1);
        __half h2 = __float2half_rn(v2), h3 = __float2half_rn(v3);
        *(__half2*)(g_ahi + (size_t)grow * DD + cc) = __halves2half2(h0, h1);
        *(__half2*)(g_alo + (size_t)grow * DD + cc) = __halves2half2(
            __float2half_rn(v0 - __half2float(h0)), __float2half_rn(v1 - __half2float(h1)));
        *(__half2*)(g_ahi + (size_t)(grow + 8) * DD + cc) = __halves2half2(h2, h3);
        *(__half2*)(g_alo + (size_t)(grow + 8) * DD + cc) = __halves2half2(
            __float2half_rn(v2 - __half2float(h2)), __float2half_rn(v3 - __half2float(h3)));
    }
}

// ---------------- elementwise / setup ----------------------------------------
#define NX  (MTOK * DD)
#define NWQ (DD * DD)
#define NWK (HKV * HD * DD)
#define NTOT (NX + NWQ + 2 * NWK + NWQ)

__global__ void split_all(const float* __restrict__ x,  const float* __restrict__ wq,
                          const float* __restrict__ wk, const float* __restrict__ wv,
                          const float* __restrict__ wo)
{
    for (int i = blockIdx.x * blockDim.x + threadIdx.x; i < NTOT; i += gridDim.x * blockDim.x) {
        const float* src; __half *hi, *lo; int o = i;
        if (o < NX)                 { src = x;  hi = g_xhi;  lo = g_xlo; }
        else if ((o -= NX)  < NWQ)  { src = wq; hi = g_wqhi; lo = g_wqlo; }
        else if ((o -= NWQ) < NWK)  { src = wk; hi = g_wkhi; lo = g_wklo; }
        else if ((o -= NWK) < NWK)  { src = wv; hi = g_wvhi; lo = g_wvlo; }
        else  { o -= NWK;             src = wo; hi = g_wohi; lo = g_wolo; }
        float v = src[o];
        __half h = __float2half_rn(v);
        hi[o] = h;
        lo[o] = __float2half_rn(v - __half2float(h));
    }
}

__global__ void rope_q_kernel(const float* __restrict__ fc, const float* __restrict__ fs)
{
    int idx = blockIdx.x * blockDim.x + threadIdx.x;    // BB*SS*HH*64 pairs
    int p = idx & 63; int rest = idx >> 6;
    int h = rest & 31; rest >>= 5;
    int s = rest & 511; int b = rest >> 9;
    float c  = fc[s * 64 + p];
    float si = fs[s * 64 + p];
    size_t o = ((size_t)(b * SS + s) * HH + h) * HD + 2 * p;
    float a  = __half2float(g_qhi[o])     + __half2float(g_qlo[o]);
    float bb = __half2float(g_qhi[o + 1]) + __half2float(g_qlo[o + 1]);
    float o0 = a * c - bb * si, o1 = a * si + bb * c;
    __half h0 = __float2half_rn(o0), h1 = __float2half_rn(o1);
    g_qhi[o] = h0;     g_qlo[o]     = __float2half_rn(o0 - __half2float(h0));
    g_qhi[o + 1] = h1; g_qlo[o + 1] = __float2half_rn(o1 - __half2float(h1));
}

__global__ void rope_k_kernel(const float* __restrict__ fc, const float* __restrict__ fs)
{
    int idx = blockIdx.x * blockDim.x + threadIdx.x;    // BB*SS*HKV*64 pairs
    int p = idx & 63; int rest = idx >> 6;
    int kv = rest & 7; rest >>= 3;
    int s = rest & 511; int b = rest >> 9;
    float c  = fc[s * 64 + p];
    float si = fs[s * 64 + p];
    size_t so = ((size_t)(b * SS + s) * HKV + kv) * HD + 2 * p;
    size_t dd = ((size_t)(b * TT + STARTP + s) * HKV + kv) * HD + 2 * p;
    float a  = __half2float(g_kthi[so])     + __half2float(g_ktlo[so]);
    float bb = __half2float(g_kthi[so + 1]) + __half2float(g_ktlo[so + 1]);
    float o0 = a * c - bb * si, o1 = a * si + bb * c;
    __half h0 = __float2half_rn(o0), h1 = __float2half_rn(o1);
    g_khi[dd] = h0;     g_klo[dd]     = __float2half_rn(o0 - __half2float(h0));
    g_khi[dd + 1] = h1; g_klo[dd + 1] = __float2half_rn(o1 - __half2float(h1));
}

__global__ void cachek_kernel(const float* __restrict__ ck)
{
    int i = blockIdx.x * blockDim.x + threadIdx.x;      // BB*STARTP*HKV*HD
    int b = i >> 19;
    size_t d = (size_t)i + (size_t)b * (STARTP * HKV * HD);
    float v = ck[i];
    __half h = __float2half_rn(v);
    g_khi[d] = h;
    g_klo[d] = __float2half_rn(v - __half2float(h));
}

__global__ void vT_build(const float* __restrict__ cv)
{
    int bkv = blockIdx.z; int b = bkv >> 3, kv = bkv & 7;
    int t0 = blockIdx.x * 32, hd0 = blockIdx.y * 32;
    __shared__ float tile[32][33];
    for (int i = threadIdx.y; i < 32; i += 8) {
        int t = t0 + i; int hd = hd0 + threadIdx.x;
        float v;
        if (t < STARTP) v = cv[(((size_t)b * STARTP + t) * HKV + kv) * HD + hd];
        else {
            size_t o = (((size_t)b * SS + (t - STARTP)) * HKV + kv) * HD + hd;
            v = __half2float(g_vthi[o]) + __half2float(g_vtlo[o]);
        }
        tile[i][threadIdx.x] = v;
    }
    __syncthreads();
    for (int i = threadIdx.y; i < 32; i += 8) {
        int hd = hd0 + i; int t = t0 + threadIdx.x;
        float v = tile[threadIdx.x][i];
        __half h = __float2half_rn(v);
        size_t o = ((size_t)bkv * HD + hd) * TT + t;
        g_vThi[o] = h;
        g_vTlo[o] = __float2half_rn(v - __half2float(h));
    }
}

// ---------------- launch -----------------------------------------------------
extern "C" void kernel_launch(void* const* d_in, const int* in_sizes, int n_in,
                              void* d_out, int out_size)
{
    const float* x  = (const float*)d_in[0];
    const float* wq = (const float*)d_in[1];
    const float* wk = (const float*)d_in[2];
    const float* wv = (const float*)d_in[3];
    const float* wo = (const float*)d_in[4];
    const float* fc = (const float*)d_in[5];
    const float* fs = (const float*)d_in[6];
    const float* ck = (const float*)d_in[7];
    const float* cv = (const float*)d_in[8];
    float* out = (float*)d_out;

    cudaFuncSetAttribute(tc_qkv,   cudaFuncAttributeMaxDynamicSharedMemorySize, DSMEM);
    cudaFuncSetAttribute(tc_wo,    cudaFuncAttributeMaxDynamicSharedMemorySize, DSMEM);
    cudaFuncSetAttribute(tc_flash, cudaFuncAttributeMaxDynamicSharedMemorySize, SMEMF);

    // 0) split all fp32 inputs to f16 hi/lo
    split_all<<<8192, 256>>>(x, wq, wk, wv, wo);

    // 1) fused Q/K/V projections (split-f16 out)
    tc_qkv<<<dim3(48, 16), 256, DSMEM>>>();

    // 2) rope + KV assembly
    rope_q_kernel<<<(BB * SS * HH * 64) / 256, 256>>>(fc, fs);
    rope_k_kernel<<<(BB * SS * HKV * 64) / 256, 256>>>(fc, fs);
    cachek_kernel<<<(BB * STARTP * HKV * HD) / 256, 256>>>(ck);
    vT_build<<<dim3(TT / 32, HD / 32, BB * HKV), dim3(32, 8)>>>(cv);

    // 3) fused attention: scores + softmax + PV -> split-f16 attn
    tc_flash<<<dim3(SS / 128, BB * HH), 256, SMEMF>>>();

    // 4) output projection -> d_out (fp32)
    tc_wo<<<dim3(32, 16), 256, DSMEM>>>(out);
}